// round 16
// baseline (speedup 1.0000x reference)
#include <cuda_runtime.h>
#include <cuda_fp16.h>
#include <cstdint>

#define NMAX 100000
#define EMAXN 1600000
#define KF 256
#define HD 128

// ---------------- scratch (device globals; no allocs allowed) ----------------
__device__ float g_ft[(size_t)NMAX * HD];   // projected features fp32 [N,128]
__device__ float g_el[NMAX * 4];            // left logits  [N,4]
__device__ float g_er[NMAX * 4];            // right logits [N,4]
__device__ int   g_cnt[NMAX];               // histogram, then scatter cursor
__device__ int   g_off[NMAX + 1];           // CSR offsets (destructively shifted by scatter)
__device__ int   g_bsum[512];               // block partial sums
__device__ int   g_boff[512];               // block exclusive prefixes
__device__ int   g_esrc[EMAXN];             // src ids bucketed by dst
__device__ int            g_arrive1, g_arrive2;
__device__ volatile int   g_flag1, g_flag2;

// ================= fp16 tensor-core GEMM (m16n8k16, fp32 accum) ==============
// ft = feat[M,256] @ fc_w[128,256]^T ; fused el/er ; fp32 ft output.
// Block tile 128x128, BK=32, 512 threads = 16 warps (4m x 4n), warp tile 32x32.
// fp32->half2 conversion once at stage time; double-buffered smem with
// register prefetch; ONE __syncthreads per K-tile.
#define BK    32
#define SMSU  20   // u32 per smem row (= 40 halves: 32 data + 8 pad)

__device__ __forceinline__ unsigned packh2(float x, float y) {
    __half2 h = __floats2half2_rn(x, y);
    return *(unsigned*)&h;
}

__global__ __launch_bounds__(512, 2) void mma_gemm_kernel(const float* __restrict__ A,
                                                          const float* __restrict__ B,
                                                          const float* __restrict__ attn_l,
                                                          const float* __restrict__ attn_r,
                                                          int M) {
    __shared__ unsigned AsU[2][128 * SMSU];
    __shared__ unsigned BsU[2][128 * SMSU];

    const int tid    = threadIdx.x;
    const int wid    = tid >> 5;      // 0..15
    const int lane   = tid & 31;
    const int warp_m = wid >> 2;      // 0..3  (32-row slice)
    const int warp_n = wid & 3;       // 0..3  (head; 32-col slice)
    const int g      = lane >> 2;     // 0..7
    const int tg     = lane & 3;      // 0..3

    const int row0 = blockIdx.x * 128;
    const int lr   = tid >> 2;        // 0..127 (staging row)
    const int lc8  = (tid & 3) * 8;   // staging col: 0,8,16,24

    float c[2][4][4];
#pragma unroll
    for (int i = 0; i < 2; i++)
#pragma unroll
        for (int j = 0; j < 4; j++)
#pragma unroll
            for (int k = 0; k < 4; k++) c[i][j][k] = 0.f;

    const int  ar = row0 + lr;
    const bool ok = (ar < M);
    const float* pa = A + (size_t)(ok ? ar : 0) * KF + lc8;
    const float* pb = B + (size_t)lr * KF + lc8;

    unsigned ra[4], rb[4];
    auto ldreg = [&](int kt) {
        float4 x0 = *(const float4*)(pa + kt);
        float4 x1 = *(const float4*)(pa + kt + 4);
        ra[0] = packh2(x0.x, x0.y); ra[1] = packh2(x0.z, x0.w);
        ra[2] = packh2(x1.x, x1.y); ra[3] = packh2(x1.z, x1.w);
        float4 y0 = *(const float4*)(pb + kt);
        float4 y1 = *(const float4*)(pb + kt + 4);
        rb[0] = packh2(y0.x, y0.y); rb[1] = packh2(y0.z, y0.w);
        rb[2] = packh2(y1.x, y1.y); rb[3] = packh2(y1.z, y1.w);
    };

    const int su = lr * SMSU + (tid & 3) * 4;   // u32 store offset

    ldreg(0);
    const int NT = KF / BK;   // 8
#pragma unroll 1
    for (int t = 0; t < NT; t++) {
        const int buf = t & 1;
        unsigned* sa = &AsU[buf][su];
        unsigned* sbp = &BsU[buf][su];
        sa[0] = ra[0]; sa[1] = ra[1]; sa[2] = ra[2]; sa[3] = ra[3];
        sbp[0] = rb[0]; sbp[1] = rb[1]; sbp[2] = rb[2]; sbp[3] = rb[3];
        __syncthreads();   // tile t visible; prior-iter reads done (double buffer)

        if (t + 1 < NT) ldreg((t + 1) * BK);   // prefetch overlaps compute

        const unsigned* Ab = &AsU[buf][0];
        const unsigned* Bb = &BsU[buf][0];
#pragma unroll
        for (int ks = 0; ks < 2; ks++) {
            const int kh = ks * 8;   // u32 (half2) offset within row
            unsigned a[2][4], b[4][2];
#pragma unroll
            for (int mt = 0; mt < 2; mt++) {
                int mb = warp_m * 32 + mt * 16;
                a[mt][0] = Ab[(mb + g)     * SMSU + kh + tg];
                a[mt][1] = Ab[(mb + g + 8) * SMSU + kh + tg];
                a[mt][2] = Ab[(mb + g)     * SMSU + kh + tg + 4];
                a[mt][3] = Ab[(mb + g + 8) * SMSU + kh + tg + 4];
            }
#pragma unroll
            for (int nt = 0; nt < 4; nt++) {
                int nb = warp_n * 32 + nt * 8;
                b[nt][0] = Bb[(nb + g) * SMSU + kh + tg];
                b[nt][1] = Bb[(nb + g) * SMSU + kh + tg + 4];
            }
#pragma unroll
            for (int mt = 0; mt < 2; mt++)
#pragma unroll
                for (int nt = 0; nt < 4; nt++) {
                    asm volatile(
                        "mma.sync.aligned.m16n8k16.row.col.f32.f16.f16.f32 "
                        "{%0,%1,%2,%3}, {%4,%5,%6,%7}, {%8,%9}, {%0,%1,%2,%3};\n"
                        : "+f"(c[mt][nt][0]), "+f"(c[mt][nt][1]),
                          "+f"(c[mt][nt][2]), "+f"(c[mt][nt][3])
                        : "r"(a[mt][0]), "r"(a[mt][1]), "r"(a[mt][2]), "r"(a[mt][3]),
                          "r"(b[nt][0]), "r"(b[nt][1]));
                }
        }
    }

    // ---- attn weights for this thread's 8 columns (within head warp_n) ----
    float wl[4][2], wr[4][2];
#pragma unroll
    for (int nt = 0; nt < 4; nt++) {
        int col = warp_n * 32 + nt * 8 + 2 * tg;
        wl[nt][0] = attn_l[col]; wl[nt][1] = attn_l[col + 1];
        wr[nt][0] = attn_r[col]; wr[nt][1] = attn_r[col + 1];
    }

    // ---- epilogue: fp32 ft stores + fused el/er ----
#pragma unroll
    for (int mt = 0; mt < 2; mt++) {
        int r0 = row0 + warp_m * 32 + mt * 16 + g;

        float el0 = 0.f, er0 = 0.f, el1 = 0.f, er1 = 0.f;
#pragma unroll
        for (int nt = 0; nt < 4; nt++) {
            el0 = fmaf(c[mt][nt][0], wl[nt][0], el0); el0 = fmaf(c[mt][nt][1], wl[nt][1], el0);
            er0 = fmaf(c[mt][nt][0], wr[nt][0], er0); er0 = fmaf(c[mt][nt][1], wr[nt][1], er0);
            el1 = fmaf(c[mt][nt][2], wl[nt][0], el1); el1 = fmaf(c[mt][nt][3], wl[nt][1], el1);
            er1 = fmaf(c[mt][nt][2], wr[nt][0], er1); er1 = fmaf(c[mt][nt][3], wr[nt][1], er1);
        }
        el0 += __shfl_xor_sync(0xffffffffu, el0, 1); el0 += __shfl_xor_sync(0xffffffffu, el0, 2);
        er0 += __shfl_xor_sync(0xffffffffu, er0, 1); er0 += __shfl_xor_sync(0xffffffffu, er0, 2);
        el1 += __shfl_xor_sync(0xffffffffu, el1, 1); el1 += __shfl_xor_sync(0xffffffffu, el1, 2);
        er1 += __shfl_xor_sync(0xffffffffu, er1, 1); er1 += __shfl_xor_sync(0xffffffffu, er1, 2);

#pragma unroll
        for (int nt = 0; nt < 4; nt++) {
            int col = warp_n * 32 + nt * 8 + 2 * tg;
            if (r0 < M)
                *(float2*)&g_ft[(size_t)r0 * HD + col] = make_float2(c[mt][nt][0], c[mt][nt][1]);
            if (r0 + 8 < M)
                *(float2*)&g_ft[(size_t)(r0 + 8) * HD + col] = make_float2(c[mt][nt][2], c[mt][nt][3]);
        }
        if (tg == 0) {
            if (r0 < M)     { g_el[r0 * 4 + warp_n] = el0;       g_er[r0 * 4 + warp_n] = er0; }
            if (r0 + 8 < M) { g_el[(r0 + 8) * 4 + warp_n] = el1; g_er[(r0 + 8) * 4 + warp_n] = er1; }
        }
    }
}

// ================= histogram (+ reset of sync state) =========================
__global__ void hist_kernel(const int* __restrict__ dst, int E) {
    if (blockIdx.x == 0 && threadIdx.x == 0) {
        g_arrive1 = 0; g_arrive2 = 0; g_flag1 = 0; g_flag2 = 0;
    }
    int e = blockIdx.x * blockDim.x + threadIdx.x;
    if (e < E) atomicAdd(&g_cnt[dst[e]], 1);
}

// ================= fused scan + scatter (single kernel, grid barriers) =======
__global__ __launch_bounds__(256) void scan_scatter_kernel(const int* __restrict__ src,
                                                           const int* __restrict__ dst,
                                                           int M, int E, int nblk) {
    __shared__ int sh[256];
    __shared__ int sh2[512];
    __shared__ int s_last;

    const int b = blockIdx.x, t = threadIdx.x;
    const int i = b * 256 + t;

    // ---- in-block inclusive scan of counts ----
    int v = (i < M) ? g_cnt[i] : 0;
    sh[t] = v;
    __syncthreads();
#pragma unroll
    for (int ofs = 1; ofs < 256; ofs <<= 1) {
        int u = (t >= ofs) ? sh[t - ofs] : 0;
        __syncthreads();
        sh[t] += u;
        __syncthreads();
    }
    if (t == 255) g_bsum[b] = sh[255];
    __threadfence();
    __syncthreads();

    // ---- grid barrier 1: last-arriving block scans the partials ----
    if (t == 0) {
        int tk = atomicAdd(&g_arrive1, 1);
        s_last = (tk == nblk - 1) ? 1 : 0;
    }
    __syncthreads();
    if (s_last) {
        int e0 = (t < nblk) ? g_bsum[t] : 0;
        int e1 = (t + 256 < nblk) ? g_bsum[t + 256] : 0;
        sh2[t] = e0; sh2[t + 256] = e1;
        __syncthreads();
#pragma unroll
        for (int ofs = 1; ofs < 512; ofs <<= 1) {
            int u0 = (t >= ofs) ? sh2[t - ofs] : 0;
            int u1 = (t + 256 >= ofs) ? sh2[t + 256 - ofs] : 0;
            __syncthreads();
            sh2[t] += u0; sh2[t + 256] += u1;
            __syncthreads();
        }
        g_boff[t] = sh2[t] - e0;               // exclusive
        g_boff[t + 256] = sh2[t + 256] - e1;
        __threadfence();
        __syncthreads();
        if (t == 0) g_flag1 = 1;
    } else {
        if (t == 0) { while (g_flag1 == 0) {} }
        __syncthreads();
    }
    __threadfence();

    // ---- write global offsets ----
    int prefix = g_boff[b];
    if (i < M) g_off[i + 1] = sh[t] + prefix;
    if (i == 0) g_off[0] = 0;
    __threadfence();
    __syncthreads();

    // ---- grid barrier 2: all offsets visible before scatter ----
    if (t == 0) {
        int tk = atomicAdd(&g_arrive2, 1);
        if (tk == nblk - 1) { __threadfence(); g_flag2 = 1; }
        else { while (g_flag2 == 0) {} }
    }
    __syncthreads();
    __threadfence();

    // ---- destructive scatter: pos = g_off[d]++, shifting g_off by one ----
    const int stride = nblk * 256;
    for (int e = i; e < E; e += stride) {
        int d = dst[e];
        int pos = atomicAdd(&g_off[d], 1);
        g_esrc[pos] = src[e];
    }
}

// ================= fused softmax + aggregate (warp per dst node) =============
// fp32 gathers (LDG.128) + packed f32x2 FMA (R9 form — validated fastest).
#define FFMA2(acc, a2, v2) \
    asm("fma.rn.f32x2 %0, %1, %2, %0;" : "+l"(acc) : "l"(a2), "l"(v2))

__global__ __launch_bounds__(256) void aggregate_kernel(float* __restrict__ out, int N) {
    int d    = (blockIdx.x * blockDim.x + threadIdx.x) >> 5;
    int lane = threadIdx.x & 31;
    if (d >= N) return;

    int beg = (d == 0) ? 0 : g_off[d - 1];
    int end = g_off[d];
    const int h     = lane >> 3;
    const float erd = g_er[d * 4 + h];
    const float* fb = g_ft + lane * 4;

    unsigned long long acc01 = 0ull, acc23 = 0ull;   // packed {f32,f32} accumulators
    float asum = 0.f;

    auto one = [&](int p_) {
        int   s = g_esrc[p_];
        float v = g_el[s * 4 + h] + erd;
        v = fmaxf(v, 0.2f * v);
        float a = __expf(v);
        asum += a;
        unsigned long long a2;
        asm("mov.b64 %0, {%1, %1};" : "=l"(a2) : "f"(a));
        ulonglong2 r = *(const ulonglong2*)(fb + ((size_t)s << 7));
        FFMA2(acc01, a2, r.x);
        FFMA2(acc23, a2, r.y);
    };

    int p = beg;
    for (; p < end && (p & 3); ++p) one(p);          // align to int4
    for (; p + 4 <= end; p += 4) {
        int4 s4 = *(const int4*)&g_esrc[p];
        float v0 = g_el[s4.x * 4 + h] + erd;
        float v1 = g_el[s4.y * 4 + h] + erd;
        float v2 = g_el[s4.z * 4 + h] + erd;
        float v3 = g_el[s4.w * 4 + h] + erd;
        v0 = fmaxf(v0, 0.2f * v0); float a0 = __expf(v0);
        v1 = fmaxf(v1, 0.2f * v1); float a1 = __expf(v1);
        v2 = fmaxf(v2, 0.2f * v2); float a2f = __expf(v2);
        v3 = fmaxf(v3, 0.2f * v3); float a3 = __expf(v3);
        asum += (a0 + a1) + (a2f + a3);
        ulonglong2 r0 = *(const ulonglong2*)(fb + ((size_t)s4.x << 7));
        ulonglong2 r1 = *(const ulonglong2*)(fb + ((size_t)s4.y << 7));
        ulonglong2 r2 = *(const ulonglong2*)(fb + ((size_t)s4.z << 7));
        ulonglong2 r3 = *(const ulonglong2*)(fb + ((size_t)s4.w << 7));
        unsigned long long p0, p1, p2, p3;
        asm("mov.b64 %0, {%1, %1};" : "=l"(p0) : "f"(a0));
        asm("mov.b64 %0, {%1, %1};" : "=l"(p1) : "f"(a1));
        asm("mov.b64 %0, {%1, %1};" : "=l"(p2) : "f"(a2f));
        asm("mov.b64 %0, {%1, %1};" : "=l"(p3) : "f"(a3));
        FFMA2(acc01, p0, r0.x); FFMA2(acc23, p0, r0.y);
        FFMA2(acc01, p1, r1.x); FFMA2(acc23, p1, r1.y);
        FFMA2(acc01, p2, r2.x); FFMA2(acc23, p2, r2.y);
        FFMA2(acc01, p3, r3.x); FFMA2(acc23, p3, r3.y);
    }
    for (; p < end; ++p) one(p);

    float inv = (asum > 0.f) ? (1.f / asum) : 0.f;
    float x0, x1, x2, x3;
    asm("mov.b64 {%0, %1}, %2;" : "=f"(x0), "=f"(x1) : "l"(acc01));
    asm("mov.b64 {%0, %1}, %2;" : "=f"(x2), "=f"(x3) : "l"(acc23));
    float4 o = make_float4(x0 * inv, x1 * inv, x2 * inv, x3 * inv);
    *(float4*)&out[(size_t)d * HD + lane * 4] = o;
}

// ================= launch ====================================================
// R9 structure (normal-priority fork); fp16 HMMA GEMM.
extern "C" void kernel_launch(void* const* d_in, const int* in_sizes, int n_in,
                              void* d_out, int out_size) {
    const float* feat   = (const float*)d_in[0];
    const float* fc_w   = (const float*)d_in[1];
    const float* attn_l = (const float*)d_in[2];
    const float* attn_r = (const float*)d_in[3];
    const int*   src    = (const int*)d_in[4];
    const int*   dst    = (const int*)d_in[5];
    float*       out    = (float*)d_out;

    int M = in_sizes[0] / KF;   // nodes
    int E = in_sizes[4];        // edges
    int nblk = (M + 255) / 256;

    void* cnt_ptr = nullptr;
    cudaGetSymbolAddress(&cnt_ptr, g_cnt);

    cudaStream_t s1;
    cudaEvent_t  ev_fork, ev_join;
    cudaStreamCreateWithFlags(&s1, cudaStreamNonBlocking);
    cudaEventCreateWithFlags(&ev_fork, cudaEventDisableTiming);
    cudaEventCreateWithFlags(&ev_join, cudaEventDisableTiming);

    // ---- fork: GEMM branch on s1 (normal priority) ----
    cudaEventRecord(ev_fork, 0);
    cudaStreamWaitEvent(s1, ev_fork, 0);
    mma_gemm_kernel<<<(M + 127) / 128, 512, 0, s1>>>(feat, fc_w, attn_l, attn_r, M);
    cudaEventRecord(ev_join, s1);

    // ---- CSR branch on main stream ----
    cudaMemsetAsync(cnt_ptr, 0, (size_t)M * sizeof(int), 0);
    hist_kernel<<<(E + 255) / 256, 256>>>(dst, E);
    scan_scatter_kernel<<<nblk, 256>>>(src, dst, M, E, nblk);

    // ---- join, then aggregate ----
    cudaStreamWaitEvent(0, ev_join, 0);
    aggregate_kernel<<<(M * 32 + 255) / 256, 256>>>(out, M);
}

// round 17
// speedup vs baseline: 1.0880x; 1.0880x over previous
#include <cuda_runtime.h>
#include <cuda_fp16.h>
#include <cstdint>

#define NMAX 100000
#define EMAXN 1600000
#define KF 256
#define HD 128

// ---------------- scratch (device globals; no allocs allowed) ----------------
__device__ float g_ft[(size_t)NMAX * HD];   // projected features fp32 [N,128]
__device__ float g_el[NMAX * 4];            // left logits  [N,4]
__device__ float g_er[NMAX * 4];            // right logits [N,4]
__device__ int   g_cnt[NMAX];               // histogram, then scatter cursor
__device__ int   g_off[NMAX + 1];           // CSR offsets (destructively shifted by scatter)
__device__ int   g_bsum[512];               // block partial sums
__device__ int   g_boff[512];               // block exclusive prefixes
__device__ int   g_esrc[EMAXN];             // src ids bucketed by dst
__device__ int            g_arrive1, g_arrive2;
__device__ volatile int   g_flag1, g_flag2;

// ================= fp16 tensor-core GEMM (m16n8k16 + ldmatrix) ===============
// ft = feat[M,256] @ fc_w[128,256]^T ; fused el/er ; fp32 ft output.
// Block tile 128x128, BK=32, 512 threads = 16 warps (4m x 4n), warp tile 32x32.
// Stage-time fp32->half2; double-buffered smem, 1 sync/tile, reg prefetch;
// fragment loads via ldmatrix.m8n8.x4 (8 per warp per tile).
#define BK    32
#define SMSU  20   // u32 per smem row (32 data halves + 8 pad halves)

__device__ __forceinline__ unsigned packh2(float x, float y) {
    __half2 h = __floats2half2_rn(x, y);
    return *(unsigned*)&h;
}

__device__ __forceinline__ void ldsm4(unsigned& r0, unsigned& r1, unsigned& r2, unsigned& r3,
                                      unsigned addr) {
    asm volatile("ldmatrix.sync.aligned.m8n8.x4.shared.b16 {%0,%1,%2,%3}, [%4];"
                 : "=r"(r0), "=r"(r1), "=r"(r2), "=r"(r3) : "r"(addr));
}

__global__ __launch_bounds__(512, 2) void mma_gemm_kernel(const float* __restrict__ A,
                                                          const float* __restrict__ B,
                                                          const float* __restrict__ attn_l,
                                                          const float* __restrict__ attn_r,
                                                          int M) {
    __shared__ unsigned AsU[2][128 * SMSU];
    __shared__ unsigned BsU[2][128 * SMSU];

    const int tid    = threadIdx.x;
    const int wid    = tid >> 5;      // 0..15
    const int lane   = tid & 31;
    const int warp_m = wid >> 2;      // 0..3  (32-row slice)
    const int warp_n = wid & 3;       // 0..3  (head; 32-col slice)
    const int g      = lane >> 2;     // 0..7
    const int tg     = lane & 3;      // 0..3

    const int row0 = blockIdx.x * 128;
    const int lr   = tid >> 2;        // 0..127 (staging row)
    const int lc8  = (tid & 3) * 8;   // staging col: 0,8,16,24 floats

    float c[2][4][4];
#pragma unroll
    for (int i = 0; i < 2; i++)
#pragma unroll
        for (int j = 0; j < 4; j++)
#pragma unroll
            for (int k = 0; k < 4; k++) c[i][j][k] = 0.f;

    const int  ar = row0 + lr;
    const bool ok = (ar < M);
    const float* pa = A + (size_t)(ok ? ar : 0) * KF + lc8;
    const float* pb = B + (size_t)lr * KF + lc8;

    unsigned ra[4], rb[4];
    auto ldreg = [&](int kt) {
        float4 x0 = *(const float4*)(pa + kt);
        float4 x1 = *(const float4*)(pa + kt + 4);
        ra[0] = packh2(x0.x, x0.y); ra[1] = packh2(x0.z, x0.w);
        ra[2] = packh2(x1.x, x1.y); ra[3] = packh2(x1.z, x1.w);
        float4 y0 = *(const float4*)(pb + kt);
        float4 y1 = *(const float4*)(pb + kt + 4);
        rb[0] = packh2(y0.x, y0.y); rb[1] = packh2(y0.z, y0.w);
        rb[2] = packh2(y1.x, y1.y); rb[3] = packh2(y1.z, y1.w);
    };

    const int su = lr * SMSU + (tid & 3) * 4;   // u32 store offset

    // ldmatrix lane addresses (u32 indices into a tile buffer)
    // A (per mt): row = warp_m*32 + mt*16 + (l&7) + ((l>>3)&1)*8 ; col = (l>>4)*4
    // B (per nt-pair p): row = warp_n*32 + p*16 + (l&7) + (l>>4)*8 ; col = ((l>>3)&1)*4
    const int a_row  = (lane & 7) + ((lane >> 3) & 1) * 8;
    const int a_col  = (lane >> 4) * 4;
    const int b_row  = (lane & 7) + (lane >> 4) * 8;
    const int b_col  = ((lane >> 3) & 1) * 4;
    unsigned aAddr[2], bAddr[2];
#pragma unroll
    for (int mt = 0; mt < 2; mt++)
        aAddr[mt] = (unsigned)__cvta_generic_to_shared(
            &AsU[0][(warp_m * 32 + mt * 16 + a_row) * SMSU + a_col]);
#pragma unroll
    for (int p = 0; p < 2; p++)
        bAddr[p] = (unsigned)__cvta_generic_to_shared(
            &BsU[0][(warp_n * 32 + p * 16 + b_row) * SMSU + b_col]);
    const unsigned bufbytes = 128 * SMSU * 4;

    ldreg(0);
    const int NT = KF / BK;   // 8
#pragma unroll 1
    for (int t = 0; t < NT; t++) {
        const int buf = t & 1;
        unsigned* sa  = &AsU[buf][su];
        unsigned* sbp = &BsU[buf][su];
        sa[0] = ra[0]; sa[1] = ra[1]; sa[2] = ra[2]; sa[3] = ra[3];
        sbp[0] = rb[0]; sbp[1] = rb[1]; sbp[2] = rb[2]; sbp[3] = rb[3];
        __syncthreads();   // tile t visible; prior-iter reads done (double buffer)

        if (t + 1 < NT) ldreg((t + 1) * BK);   // prefetch overlaps compute

        const unsigned bofs = buf * bufbytes;
#pragma unroll
        for (int ks = 0; ks < 2; ks++) {
            const unsigned kofs = bofs + ks * 32;   // ks*8 u32 = 32 bytes
            unsigned a[2][4], b[4][2];
            ldsm4(a[0][0], a[0][1], a[0][2], a[0][3], aAddr[0] + kofs);
            ldsm4(a[1][0], a[1][1], a[1][2], a[1][3], aAddr[1] + kofs);
            ldsm4(b[0][0], b[0][1], b[1][0], b[1][1], bAddr[0] + kofs);
            ldsm4(b[2][0], b[2][1], b[3][0], b[3][1], bAddr[1] + kofs);
#pragma unroll
            for (int mt = 0; mt < 2; mt++)
#pragma unroll
                for (int nt = 0; nt < 4; nt++) {
                    asm volatile(
                        "mma.sync.aligned.m16n8k16.row.col.f32.f16.f16.f32 "
                        "{%0,%1,%2,%3}, {%4,%5,%6,%7}, {%8,%9}, {%0,%1,%2,%3};\n"
                        : "+f"(c[mt][nt][0]), "+f"(c[mt][nt][1]),
                          "+f"(c[mt][nt][2]), "+f"(c[mt][nt][3])
                        : "r"(a[mt][0]), "r"(a[mt][1]), "r"(a[mt][2]), "r"(a[mt][3]),
                          "r"(b[nt][0]), "r"(b[nt][1]));
                }
        }
    }

    // ---- attn weights for this thread's 8 columns (within head warp_n) ----
    float wl[4][2], wr[4][2];
#pragma unroll
    for (int nt = 0; nt < 4; nt++) {
        int col = warp_n * 32 + nt * 8 + 2 * tg;
        wl[nt][0] = attn_l[col]; wl[nt][1] = attn_l[col + 1];
        wr[nt][0] = attn_r[col]; wr[nt][1] = attn_r[col + 1];
    }

    // ---- epilogue: fp32 ft stores + fused el/er ----
#pragma unroll
    for (int mt = 0; mt < 2; mt++) {
        int r0 = row0 + warp_m * 32 + mt * 16 + g;

        float el0 = 0.f, er0 = 0.f, el1 = 0.f, er1 = 0.f;
#pragma unroll
        for (int nt = 0; nt < 4; nt++) {
            el0 = fmaf(c[mt][nt][0], wl[nt][0], el0); el0 = fmaf(c[mt][nt][1], wl[nt][1], el0);
            er0 = fmaf(c[mt][nt][0], wr[nt][0], er0); er0 = fmaf(c[mt][nt][1], wr[nt][1], er0);
            el1 = fmaf(c[mt][nt][2], wl[nt][0], el1); el1 = fmaf(c[mt][nt][3], wl[nt][1], el1);
            er1 = fmaf(c[mt][nt][2], wr[nt][0], er1); er1 = fmaf(c[mt][nt][3], wr[nt][1], er1);
        }
        el0 += __shfl_xor_sync(0xffffffffu, el0, 1); el0 += __shfl_xor_sync(0xffffffffu, el0, 2);
        er0 += __shfl_xor_sync(0xffffffffu, er0, 1); er0 += __shfl_xor_sync(0xffffffffu, er0, 2);
        el1 += __shfl_xor_sync(0xffffffffu, el1, 1); el1 += __shfl_xor_sync(0xffffffffu, el1, 2);
        er1 += __shfl_xor_sync(0xffffffffu, er1, 1); er1 += __shfl_xor_sync(0xffffffffu, er1, 2);

#pragma unroll
        for (int nt = 0; nt < 4; nt++) {
            int col = warp_n * 32 + nt * 8 + 2 * tg;
            if (r0 < M)
                *(float2*)&g_ft[(size_t)r0 * HD + col] = make_float2(c[mt][nt][0], c[mt][nt][1]);
            if (r0 + 8 < M)
                *(float2*)&g_ft[(size_t)(r0 + 8) * HD + col] = make_float2(c[mt][nt][2], c[mt][nt][3]);
        }
        if (tg == 0) {
            if (r0 < M)     { g_el[r0 * 4 + warp_n] = el0;       g_er[r0 * 4 + warp_n] = er0; }
            if (r0 + 8 < M) { g_el[(r0 + 8) * 4 + warp_n] = el1; g_er[(r0 + 8) * 4 + warp_n] = er1; }
        }
    }
}

// ================= histogram (+ reset of sync state) =========================
__global__ void hist_kernel(const int* __restrict__ dst, int E) {
    if (blockIdx.x == 0 && threadIdx.x == 0) {
        g_arrive1 = 0; g_arrive2 = 0; g_flag1 = 0; g_flag2 = 0;
    }
    int e = blockIdx.x * blockDim.x + threadIdx.x;
    if (e < E) atomicAdd(&g_cnt[dst[e]], 1);
}

// ================= fused scan + scatter (single kernel, grid barriers) =======
__global__ __launch_bounds__(256) void scan_scatter_kernel(const int* __restrict__ src,
                                                           const int* __restrict__ dst,
                                                           int M, int E, int nblk) {
    __shared__ int sh[256];
    __shared__ int sh2[512];
    __shared__ int s_last;

    const int b = blockIdx.x, t = threadIdx.x;
    const int i = b * 256 + t;

    // ---- in-block inclusive scan of counts ----
    int v = (i < M) ? g_cnt[i] : 0;
    sh[t] = v;
    __syncthreads();
#pragma unroll
    for (int ofs = 1; ofs < 256; ofs <<= 1) {
        int u = (t >= ofs) ? sh[t - ofs] : 0;
        __syncthreads();
        sh[t] += u;
        __syncthreads();
    }
    if (t == 255) g_bsum[b] = sh[255];
    __threadfence();
    __syncthreads();

    // ---- grid barrier 1: last-arriving block scans the partials ----
    if (t == 0) {
        int tk = atomicAdd(&g_arrive1, 1);
        s_last = (tk == nblk - 1) ? 1 : 0;
    }
    __syncthreads();
    if (s_last) {
        int e0 = (t < nblk) ? g_bsum[t] : 0;
        int e1 = (t + 256 < nblk) ? g_bsum[t + 256] : 0;
        sh2[t] = e0; sh2[t + 256] = e1;
        __syncthreads();
#pragma unroll
        for (int ofs = 1; ofs < 512; ofs <<= 1) {
            int u0 = (t >= ofs) ? sh2[t - ofs] : 0;
            int u1 = (t + 256 >= ofs) ? sh2[t + 256 - ofs] : 0;
            __syncthreads();
            sh2[t] += u0; sh2[t + 256] += u1;
            __syncthreads();
        }
        g_boff[t] = sh2[t] - e0;               // exclusive
        g_boff[t + 256] = sh2[t + 256] - e1;
        __threadfence();
        __syncthreads();
        if (t == 0) g_flag1 = 1;
    } else {
        if (t == 0) { while (g_flag1 == 0) {} }
        __syncthreads();
    }
    __threadfence();

    // ---- write global offsets ----
    int prefix = g_boff[b];
    if (i < M) g_off[i + 1] = sh[t] + prefix;
    if (i == 0) g_off[0] = 0;
    __threadfence();
    __syncthreads();

    // ---- grid barrier 2: all offsets visible before scatter ----
    if (t == 0) {
        int tk = atomicAdd(&g_arrive2, 1);
        if (tk == nblk - 1) { __threadfence(); g_flag2 = 1; }
        else { while (g_flag2 == 0) {} }
    }
    __syncthreads();
    __threadfence();

    // ---- destructive scatter: pos = g_off[d]++, shifting g_off by one ----
    const int stride = nblk * 256;
    for (int e = i; e < E; e += stride) {
        int d = dst[e];
        int pos = atomicAdd(&g_off[d], 1);
        g_esrc[pos] = src[e];
    }
}

// ================= fused softmax + aggregate (warp per dst node) =============
// fp32 gathers (LDG.128) + packed f32x2 FMA (R9 form — validated fastest).
#define FFMA2(acc, a2, v2) \
    asm("fma.rn.f32x2 %0, %1, %2, %0;" : "+l"(acc) : "l"(a2), "l"(v2))

__global__ __launch_bounds__(256) void aggregate_kernel(float* __restrict__ out, int N) {
    int d    = (blockIdx.x * blockDim.x + threadIdx.x) >> 5;
    int lane = threadIdx.x & 31;
    if (d >= N) return;

    int beg = (d == 0) ? 0 : g_off[d - 1];
    int end = g_off[d];
    const int h     = lane >> 3;
    const float erd = g_er[d * 4 + h];
    const float* fb = g_ft + lane * 4;

    unsigned long long acc01 = 0ull, acc23 = 0ull;   // packed {f32,f32} accumulators
    float asum = 0.f;

    auto one = [&](int p_) {
        int   s = g_esrc[p_];
        float v = g_el[s * 4 + h] + erd;
        v = fmaxf(v, 0.2f * v);
        float a = __expf(v);
        asum += a;
        unsigned long long a2;
        asm("mov.b64 %0, {%1, %1};" : "=l"(a2) : "f"(a));
        ulonglong2 r = *(const ulonglong2*)(fb + ((size_t)s << 7));
        FFMA2(acc01, a2, r.x);
        FFMA2(acc23, a2, r.y);
    };

    int p = beg;
    for (; p < end && (p & 3); ++p) one(p);          // align to int4
    for (; p + 4 <= end; p += 4) {
        int4 s4 = *(const int4*)&g_esrc[p];
        float v0 = g_el[s4.x * 4 + h] + erd;
        float v1 = g_el[s4.y * 4 + h] + erd;
        float v2 = g_el[s4.z * 4 + h] + erd;
        float v3 = g_el[s4.w * 4 + h] + erd;
        v0 = fmaxf(v0, 0.2f * v0); float a0 = __expf(v0);
        v1 = fmaxf(v1, 0.2f * v1); float a1 = __expf(v1);
        v2 = fmaxf(v2, 0.2f * v2); float a2f = __expf(v2);
        v3 = fmaxf(v3, 0.2f * v3); float a3 = __expf(v3);
        asum += (a0 + a1) + (a2f + a3);
        ulonglong2 r0 = *(const ulonglong2*)(fb + ((size_t)s4.x << 7));
        ulonglong2 r1 = *(const ulonglong2*)(fb + ((size_t)s4.y << 7));
        ulonglong2 r2 = *(const ulonglong2*)(fb + ((size_t)s4.z << 7));
        ulonglong2 r3 = *(const ulonglong2*)(fb + ((size_t)s4.w << 7));
        unsigned long long p0, p1, p2, p3;
        asm("mov.b64 %0, {%1, %1};" : "=l"(p0) : "f"(a0));
        asm("mov.b64 %0, {%1, %1};" : "=l"(p1) : "f"(a1));
        asm("mov.b64 %0, {%1, %1};" : "=l"(p2) : "f"(a2f));
        asm("mov.b64 %0, {%1, %1};" : "=l"(p3) : "f"(a3));
        FFMA2(acc01, p0, r0.x); FFMA2(acc23, p0, r0.y);
        FFMA2(acc01, p1, r1.x); FFMA2(acc23, p1, r1.y);
        FFMA2(acc01, p2, r2.x); FFMA2(acc23, p2, r2.y);
        FFMA2(acc01, p3, r3.x); FFMA2(acc23, p3, r3.y);
    }
    for (; p < end; ++p) one(p);

    float inv = (asum > 0.f) ? (1.f / asum) : 0.f;
    float x0, x1, x2, x3;
    asm("mov.b64 {%0, %1}, %2;" : "=f"(x0), "=f"(x1) : "l"(acc01));
    asm("mov.b64 {%0, %1}, %2;" : "=f"(x2), "=f"(x3) : "l"(acc23));
    float4 o = make_float4(x0 * inv, x1 * inv, x2 * inv, x3 * inv);
    *(float4*)&out[(size_t)d * HD + lane * 4] = o;
}

// ================= launch ====================================================
// R9 structure (normal-priority fork); ldmatrix fp16 HMMA GEMM.
extern "C" void kernel_launch(void* const* d_in, const int* in_sizes, int n_in,
                              void* d_out, int out_size) {
    const float* feat   = (const float*)d_in[0];
    const float* fc_w   = (const float*)d_in[1];
    const float* attn_l = (const float*)d_in[2];
    const float* attn_r = (const float*)d_in[3];
    const int*   src    = (const int*)d_in[4];
    const int*   dst    = (const int*)d_in[5];
    float*       out    = (float*)d_out;

    int M = in_sizes[0] / KF;   // nodes
    int E = in_sizes[4];        // edges
    int nblk = (M + 255) / 256;

    void* cnt_ptr = nullptr;
    cudaGetSymbolAddress(&cnt_ptr, g_cnt);

    cudaStream_t s1;
    cudaEvent_t  ev_fork, ev_join;
    cudaStreamCreateWithFlags(&s1, cudaStreamNonBlocking);
    cudaEventCreateWithFlags(&ev_fork, cudaEventDisableTiming);
    cudaEventCreateWithFlags(&ev_join, cudaEventDisableTiming);

    // ---- fork: GEMM branch on s1 (normal priority) ----
    cudaEventRecord(ev_fork, 0);
    cudaStreamWaitEvent(s1, ev_fork, 0);
    mma_gemm_kernel<<<(M + 127) / 128, 512, 0, s1>>>(feat, fc_w, attn_l, attn_r, M);
    cudaEventRecord(ev_join, s1);

    // ---- CSR branch on main stream ----
    cudaMemsetAsync(cnt_ptr, 0, (size_t)M * sizeof(int), 0);
    hist_kernel<<<(E + 255) / 256, 256>>>(dst, E);
    scan_scatter_kernel<<<nblk, 256>>>(src, dst, M, E, nblk);

    // ---- join, then aggregate ----
    cudaStreamWaitEvent(0, ev_join, 0);
    aggregate_kernel<<<(M * 32 + 255) / 256, 256>>>(out, M);
}